// round 5
// baseline (speedup 1.0000x reference)
#include <cuda_runtime.h>
#include <cstdint>
#include <cstddef>

#define NB    16
#define CC    192
#define HH    56
#define WW    56
#define HWP   (HH*WW)          // 3136
#define NPIX  (NB*HWP)         // 50176
#define HEADS 6
#define CHN   32
#define KT    486              // 81 * 6
#define KTP   648              // padded: 54 groups * 12
#define SCALE 0.17677669529663689f   // 32^-0.5

// ---------------- scratch (device globals; no runtime allocation) -------------
__device__ float g_v   [NB*CC*HWP];                 // value projection    (38.5 MB)
__device__ float g_att [(size_t)NPIX*KTP];          // softmaxed att, padded (130 MB)
__device__ float g_fold[NB*CC*HWP];                 // folded result       (38.5 MB)
__device__ float g_wpad[CC*KTP];                    // padded Wa           (497 KB)

// ---------------- packed f32x2 helpers ---------------------------------------
#define FMA2(acc,a,b) asm("fma.rn.f32x2 %0, %1, %2, %0;" : "+l"(acc) : "l"(a), "l"(b))

__device__ __forceinline__ unsigned long long pack2(float x, float y) {
    unsigned long long r;
    asm("mov.b64 %0, {%1, %2};" : "=l"(r) : "r"(__float_as_uint(x)), "r"(__float_as_uint(y)));
    return r;
}
__device__ __forceinline__ void unpack2(unsigned long long v, float& x, float& y) {
    unsigned int lo, hi;
    asm("mov.b64 {%0, %1}, %2;" : "=r"(lo), "=r"(hi) : "l"(v));
    x = __uint_as_float(lo); y = __uint_as_float(hi);
}

// ============================================================================
// Wa pre-pad: [192][486] -> [192][648], group g's 9 cols at 12g..12g+8, pad 0.
// ============================================================================
__global__ void pad_wa_kernel(const float* __restrict__ Wa, float* __restrict__ Wp)
{
    int i = blockIdx.x * 256 + threadIdx.x;
    if (i >= CC*KTP) return;
    int c = i / KTP, col = i - c*KTP;
    int g = col / 12, u = col - g*12;
    Wp[i] = (u < 9) ? Wa[c*KT + g*9 + u] : 0.0f;
}

// ============================================================================
// Kernel A/D: 192x192 pointwise GEMM, SIMT outer-product tiling. (unchanged)
// ============================================================================
__global__ void __launch_bounds__(192, 3) gemm192_kernel(
    const float* __restrict__ X, const float* __restrict__ Wm,
    const float* __restrict__ bias, float* __restrict__ Out)
{
    __shared__ float xs[48][128];
    __shared__ float ws[48][96];
    const int tid  = threadIdx.x;
    const int b    = blockIdx.x;
    const int pt   = b >> 1;
    const int dt   = b & 1;
    const int g0   = pt * 128;
    const int dbase= dt * 96;
    const int warp = tid >> 5, lane = tid & 31;
    const int wd   = warp % 3, wp = warp / 3;
    const int ld   = lane >> 3, lp = lane & 7;
    const int d0   = wd*32 + ld*8;
    const int p0   = wp*64 + lp*8;

    unsigned long long acc[8][4];
    #pragma unroll
    for (int di = 0; di < 8; di++) {
        float bb = bias ? bias[dbase + d0 + di] : 0.0f;
        unsigned long long b2 = pack2(bb, bb);
        #pragma unroll
        for (int pp = 0; pp < 4; pp++) acc[di][pp] = b2;
    }

    for (int kc = 0; kc < 4; kc++) {
        __syncthreads();
        #pragma unroll
        for (int s = 0; s < 8; s++) {
            int idx = tid + s*192;
            int k = idx >> 5, p4 = idx & 31;
            int g = g0 + p4*4;
            int n = g / HWP, hw = g - n*HWP;
            *(float4*)&xs[k][p4*4] =
                *(const float4*)&X[((size_t)(n*CC) + kc*48 + k)*HWP + hw];
        }
        #pragma unroll
        for (int s = 0; s < 6; s++) {
            int idx = tid + s*192;
            int k = idx / 24, c4 = idx - k*24;
            *(float4*)&ws[k][c4*4] =
                *(const float4*)&Wm[(size_t)(kc*48 + k)*192 + dbase + c4*4];
        }
        __syncthreads();

        #pragma unroll 4
        for (int r = 0; r < 48; r++) {
            float4 wa = *(const float4*)&ws[r][d0];
            float4 wb = *(const float4*)&ws[r][d0+4];
            ulonglong2 xv0 = *(const ulonglong2*)&xs[r][p0];
            ulonglong2 xv1 = *(const ulonglong2*)&xs[r][p0+4];
            unsigned long long xp[4] = {xv0.x, xv0.y, xv1.x, xv1.y};
            unsigned long long w2[8];
            w2[0]=pack2(wa.x,wa.x); w2[1]=pack2(wa.y,wa.y);
            w2[2]=pack2(wa.z,wa.z); w2[3]=pack2(wa.w,wa.w);
            w2[4]=pack2(wb.x,wb.x); w2[5]=pack2(wb.y,wb.y);
            w2[6]=pack2(wb.z,wb.z); w2[7]=pack2(wb.w,wb.w);
            #pragma unroll
            for (int di = 0; di < 8; di++)
                #pragma unroll
                for (int pp = 0; pp < 4; pp++)
                    FMA2(acc[di][pp], xp[pp], w2[di]);
        }
    }

    #pragma unroll
    for (int s = 0; s < 2; s++) {
        int g = g0 + p0 + s*4;
        int n = g / HWP, hw = g - n*HWP;
        #pragma unroll
        for (int di = 0; di < 8; di++) {
            ulonglong2 uv; uv.x = acc[di][2*s]; uv.y = acc[di][2*s+1];
            *(ulonglong2*)&Out[((size_t)(n*CC) + dbase + d0 + di)*HWP + hw] = uv;
        }
    }
}

// ============================================================================
// Kernel B: attention logits GEMM + fused register softmax. (unchanged)
// ============================================================================
#define ATT_SMEM_BYTES ((32*64 + 32*KTP)*4)      // 91136

__global__ void __launch_bounds__(864, 1) att_kernel(
    const float* __restrict__ X, const float* __restrict__ Wpad,
    const float* __restrict__ ba, float* __restrict__ Att)
{
    extern __shared__ float sm[];
    float* xs = sm;                 // [32][64]
    float* ws = sm + 32*64;         // [32][648]
    const int tid = threadIdx.x;
    const int cg  = tid >> 4;       // 0..53
    const int pg  = tid & 15;       // 0..15 -> px [4pg, 4pg+4)
    const int bb  = blockIdx.x;
    const int n   = bb / 49;
    const int hw0 = (bb - n*49) * 64;

    unsigned long long acc[9][2];
    #pragma unroll
    for (int u = 0; u < 9; u++) {
        float bv = ba[9*cg + u];
        unsigned long long b2 = pack2(bv, bv);
        acc[u][0] = b2; acc[u][1] = b2;
    }

    for (int kc = 0; kc < 6; kc++) {
        __syncthreads();
        if (tid < 512) {
            int k = tid >> 4, p4 = tid & 15;
            *(float4*)&xs[k*64 + p4*4] =
                *(const float4*)&X[((size_t)(n*CC) + kc*32 + k)*HWP + hw0 + p4*4];
        }
        #pragma unroll
        for (int s = 0; s < 6; s++) {
            int idx = tid + s*864;
            int k = idx / 162, c4 = idx - k*162;
            *(float4*)&ws[k*KTP + c4*4] =
                *(const float4*)&Wpad[(size_t)(kc*32 + k)*KTP + c4*4];
        }
        __syncthreads();

        #pragma unroll 2
        for (int r = 0; r < 32; r++) {
            float4 q0 = *(const float4*)&ws[r*KTP + 12*cg];
            float4 q1 = *(const float4*)&ws[r*KTP + 12*cg + 4];
            float  q8 = ws[r*KTP + 12*cg + 8];
            ulonglong2 xv = *(const ulonglong2*)&xs[r*64 + 4*pg];
            unsigned long long xp0 = xv.x, xp1 = xv.y;
            float wv[9] = {q0.x,q0.y,q0.z,q0.w,q1.x,q1.y,q1.z,q1.w,q8};
            #pragma unroll
            for (int u = 0; u < 9; u++) {
                unsigned long long w2 = pack2(wv[u], wv[u]);
                FMA2(acc[u][0], xp0, w2);
                FMA2(acc[u][1], xp1, w2);
            }
        }
    }

    #pragma unroll
    for (int pp = 0; pp < 2; pp++) {
        float z0[9], z1[9];
        #pragma unroll
        for (int u = 0; u < 9; u++) unpack2(acc[u][pp], z0[u], z1[u]);
        #pragma unroll
        for (int half = 0; half < 2; half++) {
            float* z = half ? z1 : z0;
            float m = z[0];
            #pragma unroll
            for (int u = 1; u < 9; u++) m = fmaxf(m, z[u]);
            float e[9], s = 0.0f;
            #pragma unroll
            for (int u = 0; u < 9; u++) { e[u] = __expf((z[u]-m)*SCALE); s += e[u]; }
            float inv = 1.0f / s;
            int px = 4*pg + 2*pp + half;
            float* dst = Att + ((size_t)(n*HWP) + hw0 + px)*KTP + cg*12;
            float4 f0 = {e[0]*inv, e[1]*inv, e[2]*inv, e[3]*inv};
            float4 f1 = {e[4]*inv, e[5]*inv, e[6]*inv, e[7]*inv};
            float4 f2 = {e[8]*inv, 0.0f, 0.0f, 0.0f};
            *(float4*)(dst)     = f0;
            *(float4*)(dst + 4) = f1;
            *(float4*)(dst + 8) = f2;
        }
    }
}

// ============================================================================
// Kernel C: aggregation + fold, 5x5 collapsed stencil, head-split for occ.
// Each block: one 8x8 tile x 3 heads (96 channels = 48 chpairs).
//   - vsm: 48 chpairs x 145 ull = 55.7KB -> 2 blocks/SM (24 warps)
//   - att reads partition exactly by head -> no duplicated DRAM traffic
//   - direct STG epilogue (no fsm staging, no extra sync/pass)
// 384 threads = (half in 2) x (h3 in 3) x (q in 64); each thread: build W2
// once (halves hit L1 on the duplicate), then 8 chpairs x 25 FMA2.
// ============================================================================
#define AGG_SMEM_BYTES (48*145*8)                // 55680

__global__ void __launch_bounds__(384, 2) agg_kernel(
    const float* __restrict__ V, const float* __restrict__ Att,
    float* __restrict__ Fold)
{
    extern __shared__ char smraw[];
    unsigned long long* vsm2 = (unsigned long long*)smraw;      // [48][145]
    const int tid = threadIdx.x;
    const int blk = blockIdx.x;
    const int hb  = blk & 1;            // head half: heads 3hb..3hb+2
    const int t2  = blk >> 1;
    const int n   = t2 / 49;
    const int tt  = t2 - n*49;
    const int y0  = (tt / 7) * 8, x0 = (tt % 7) * 8;
    const int cbase = hb * 96;          // first channel this block owns

    // load v window for this block's 96 channels as 48 channel pairs
    for (int i = tid; i < 48*144; i += 384) {
        int cp = i / 144, pos = i - cp*144;
        int ly = pos / 12, lx = pos - ly*12;
        int gy = y0 - 2 + ly, gx = x0 - 2 + lx;
        float a = 0.0f, b = 0.0f;
        if (gy >= 0 && gy < HH && gx >= 0 && gx < WW) {
            const float* vb = &V[((size_t)(n*CC) + cbase + 2*cp)*HWP + gy*WW + gx];
            a = vb[0]; b = vb[HWP];
        }
        vsm2[cp*145 + pos] = pack2(a, b);
    }
    __syncthreads();

    {
        const int g    = tid >> 6;          // 0..5
        const int q    = tid & 63;
        const int h3   = g % 3;             // head within block
        const int half = g / 3;             // channel half within head
        const int head = hb*3 + h3;
        const int qy = q >> 3, qx = q & 7;
        const int gy = y0 + qy, gx = x0 + qx;

        // build collapsed 5x5 stencil from up to 9 neighbor att rows
        float W2[25];
        #pragma unroll
        for (int p = 0; p < 25; p++) W2[p] = 0.0f;
        #pragma unroll
        for (int i = 0; i < 3; i++)
        #pragma unroll
        for (int j = 0; j < 3; j++) {
            int py = gy + 1 - i, px = gx + 1 - j;
            if (py >= 0 && py < HH && px >= 0 && px < WW) {
                const float* ab = Att + ((size_t)n*HWP + py*WW + px)*KTP
                                      + head*108 + (i*3+j)*12;
                float4 a0 = *(const float4*)(ab);
                float4 a1 = *(const float4*)(ab + 4);
                float  a8 = ab[8];
                float av[9] = {a0.x,a0.y,a0.z,a0.w,a1.x,a1.y,a1.z,a1.w,a8};
                #pragma unroll
                for (int a = 0; a < 3; a++)
                #pragma unroll
                for (int b = 0; b < 3; b++)
                    W2[(a-i+2)*5 + (b-j+2)] += av[a*3+b];
            }
        }
        unsigned long long w22[25];
        #pragma unroll
        for (int p = 0; p < 25; p++) w22[p] = pack2(W2[p], W2[p]);

        const int pos0 = qy*12 + qx;
        float* foutbase = Fold + ((size_t)(n*CC) + cbase)*HWP + gy*WW + gx;
        #pragma unroll 2
        for (int c8 = 0; c8 < 8; c8++) {
            const int cpl = h3*16 + half*8 + c8;     // block-local chpair
            const unsigned long long* vb = vsm2 + cpl*145 + pos0;
            unsigned long long acA = 0ull, acB = 0ull;
            #pragma unroll
            for (int p = 0; p < 25; p++) {
                const int off = (p/5)*12 + (p%5);
                if (p & 1) { FMA2(acB, vb[off], w22[p]); }
                else       { FMA2(acA, vb[off], w22[p]); }
            }
            float xa, ya, xb, yb;
            unpack2(acA, xa, ya); unpack2(acB, xb, yb);
            foutbase[(size_t)(2*cpl    )*HWP] = xa + xb;
            foutbase[(size_t)(2*cpl + 1)*HWP] = ya + yb;
        }
    }
}

// ============================================================================
// Launch
// ============================================================================
extern "C" void kernel_launch(void* const* d_in, const int* in_sizes, int n_in,
                              void* d_out, int out_size)
{
    const float* x  = (const float*)d_in[0];
    const float* Wv = (const float*)d_in[1];
    const float* Wa = (const float*)d_in[2];
    const float* ba = (const float*)d_in[3];
    const float* Wp = (const float*)d_in[4];
    const float* bp = (const float*)d_in[5];
    float* out = (float*)d_out;

    float *vp, *ap, *fp, *wpad;
    cudaGetSymbolAddress((void**)&vp, g_v);
    cudaGetSymbolAddress((void**)&ap, g_att);
    cudaGetSymbolAddress((void**)&fp, g_fold);
    cudaGetSymbolAddress((void**)&wpad, g_wpad);

    cudaFuncSetAttribute(att_kernel, cudaFuncAttributeMaxDynamicSharedMemorySize, ATT_SMEM_BYTES);
    cudaFuncSetAttribute(agg_kernel, cudaFuncAttributeMaxDynamicSharedMemorySize, AGG_SMEM_BYTES);

    // pad Wa -> [192][648]
    pad_wa_kernel<<<(CC*KTP + 255)/256, 256>>>(Wa, wpad);
    // value projection: v = x @ Wv
    gemm192_kernel<<<392*2, 192>>>(x, Wv, nullptr, vp);
    // attention logits + fused softmax (padded output)
    att_kernel<<<NB*49, 864, ATT_SMEM_BYTES>>>(x, wpad, ba, ap);
    // aggregation + fold (collapsed 5x5 stencil, head-split blocks)
    agg_kernel<<<NB*49*2, 384, AGG_SMEM_BYTES>>>(vp, ap, fp);
    // output projection: out = folded @ Wp + bp
    gemm192_kernel<<<392*2, 192>>>(fp, Wp, bp, out);
}

// round 6
// speedup vs baseline: 1.4454x; 1.4454x over previous
#include <cuda_runtime.h>
#include <cstdint>
#include <cstddef>

#define NB    16
#define CC    192
#define HH    56
#define WW    56
#define HWP   (HH*WW)          // 3136
#define NPIX  (NB*HWP)         // 50176
#define HEADS 6
#define CHN   32
#define KT    486              // 81 * 6
#define KTP   648              // padded: 54 groups * 12
#define SCALE 0.17677669529663689f   // 32^-0.5

// ---------------- scratch (device globals; no runtime allocation) -------------
__device__ float g_v   [NB*CC*HWP];                 // value projection    (38.5 MB)
__device__ float g_att [(size_t)NPIX*KTP];          // softmaxed att, padded (130 MB)
__device__ float g_fold[NB*CC*HWP];                 // folded result       (38.5 MB)
__device__ float g_wpad[CC*KTP];                    // padded Wa           (497 KB)

// ---------------- packed f32x2 helpers ---------------------------------------
#define FMA2(acc,a,b) asm("fma.rn.f32x2 %0, %1, %2, %0;" : "+l"(acc) : "l"(a), "l"(b))

__device__ __forceinline__ unsigned long long pack2(float x, float y) {
    unsigned long long r;
    asm("mov.b64 %0, {%1, %2};" : "=l"(r) : "r"(__float_as_uint(x)), "r"(__float_as_uint(y)));
    return r;
}
__device__ __forceinline__ void unpack2(unsigned long long v, float& x, float& y) {
    unsigned int lo, hi;
    asm("mov.b64 {%0, %1}, %2;" : "=r"(lo), "=r"(hi) : "l"(v));
    x = __uint_as_float(lo); y = __uint_as_float(hi);
}

// ============================================================================
// Wa pre-pad: [192][486] -> [192][648], group g's 9 cols at 12g..12g+8, pad 0.
// ============================================================================
__global__ void pad_wa_kernel(const float* __restrict__ Wa, float* __restrict__ Wp)
{
    int i = blockIdx.x * 256 + threadIdx.x;
    if (i >= CC*KTP) return;
    int c = i / KTP, col = i - c*KTP;
    int g = col / 12, u = col - g*12;
    Wp[i] = (u < 9) ? Wa[c*KT + g*9 + u] : 0.0f;
}

// ============================================================================
// Kernel A/D: 192x192 pointwise GEMM, SIMT outer-product tiling. (unchanged)
// ============================================================================
__global__ void __launch_bounds__(192, 3) gemm192_kernel(
    const float* __restrict__ X, const float* __restrict__ Wm,
    const float* __restrict__ bias, float* __restrict__ Out)
{
    __shared__ float xs[48][128];
    __shared__ float ws[48][96];
    const int tid  = threadIdx.x;
    const int b    = blockIdx.x;
    const int pt   = b >> 1;
    const int dt   = b & 1;
    const int g0   = pt * 128;
    const int dbase= dt * 96;
    const int warp = tid >> 5, lane = tid & 31;
    const int wd   = warp % 3, wp = warp / 3;
    const int ld   = lane >> 3, lp = lane & 7;
    const int d0   = wd*32 + ld*8;
    const int p0   = wp*64 + lp*8;

    unsigned long long acc[8][4];
    #pragma unroll
    for (int di = 0; di < 8; di++) {
        float bb = bias ? bias[dbase + d0 + di] : 0.0f;
        unsigned long long b2 = pack2(bb, bb);
        #pragma unroll
        for (int pp = 0; pp < 4; pp++) acc[di][pp] = b2;
    }

    for (int kc = 0; kc < 4; kc++) {
        __syncthreads();
        #pragma unroll
        for (int s = 0; s < 8; s++) {
            int idx = tid + s*192;
            int k = idx >> 5, p4 = idx & 31;
            int g = g0 + p4*4;
            int n = g / HWP, hw = g - n*HWP;
            *(float4*)&xs[k][p4*4] =
                *(const float4*)&X[((size_t)(n*CC) + kc*48 + k)*HWP + hw];
        }
        #pragma unroll
        for (int s = 0; s < 6; s++) {
            int idx = tid + s*192;
            int k = idx / 24, c4 = idx - k*24;
            *(float4*)&ws[k][c4*4] =
                *(const float4*)&Wm[(size_t)(kc*48 + k)*192 + dbase + c4*4];
        }
        __syncthreads();

        #pragma unroll 4
        for (int r = 0; r < 48; r++) {
            float4 wa = *(const float4*)&ws[r][d0];
            float4 wb = *(const float4*)&ws[r][d0+4];
            ulonglong2 xv0 = *(const ulonglong2*)&xs[r][p0];
            ulonglong2 xv1 = *(const ulonglong2*)&xs[r][p0+4];
            unsigned long long xp[4] = {xv0.x, xv0.y, xv1.x, xv1.y};
            unsigned long long w2[8];
            w2[0]=pack2(wa.x,wa.x); w2[1]=pack2(wa.y,wa.y);
            w2[2]=pack2(wa.z,wa.z); w2[3]=pack2(wa.w,wa.w);
            w2[4]=pack2(wb.x,wb.x); w2[5]=pack2(wb.y,wb.y);
            w2[6]=pack2(wb.z,wb.z); w2[7]=pack2(wb.w,wb.w);
            #pragma unroll
            for (int di = 0; di < 8; di++)
                #pragma unroll
                for (int pp = 0; pp < 4; pp++)
                    FMA2(acc[di][pp], xp[pp], w2[di]);
        }
    }

    #pragma unroll
    for (int s = 0; s < 2; s++) {
        int g = g0 + p0 + s*4;
        int n = g / HWP, hw = g - n*HWP;
        #pragma unroll
        for (int di = 0; di < 8; di++) {
            ulonglong2 uv; uv.x = acc[di][2*s]; uv.y = acc[di][2*s+1];
            *(ulonglong2*)&Out[((size_t)(n*CC) + dbase + d0 + di)*HWP + hw] = uv;
        }
    }
}

// ============================================================================
// Kernel B: attention logits GEMM + fused register softmax. (unchanged)
// ============================================================================
#define ATT_SMEM_BYTES ((32*64 + 32*KTP)*4)      // 91136

__global__ void __launch_bounds__(864, 1) att_kernel(
    const float* __restrict__ X, const float* __restrict__ Wpad,
    const float* __restrict__ ba, float* __restrict__ Att)
{
    extern __shared__ float sm[];
    float* xs = sm;                 // [32][64]
    float* ws = sm + 32*64;         // [32][648]
    const int tid = threadIdx.x;
    const int cg  = tid >> 4;       // 0..53
    const int pg  = tid & 15;       // 0..15 -> px [4pg, 4pg+4)
    const int bb  = blockIdx.x;
    const int n   = bb / 49;
    const int hw0 = (bb - n*49) * 64;

    unsigned long long acc[9][2];
    #pragma unroll
    for (int u = 0; u < 9; u++) {
        float bv = ba[9*cg + u];
        unsigned long long b2 = pack2(bv, bv);
        acc[u][0] = b2; acc[u][1] = b2;
    }

    for (int kc = 0; kc < 6; kc++) {
        __syncthreads();
        if (tid < 512) {
            int k = tid >> 4, p4 = tid & 15;
            *(float4*)&xs[k*64 + p4*4] =
                *(const float4*)&X[((size_t)(n*CC) + kc*32 + k)*HWP + hw0 + p4*4];
        }
        #pragma unroll
        for (int s = 0; s < 6; s++) {
            int idx = tid + s*864;
            int k = idx / 162, c4 = idx - k*162;
            *(float4*)&ws[k*KTP + c4*4] =
                *(const float4*)&Wpad[(size_t)(kc*32 + k)*KTP + c4*4];
        }
        __syncthreads();

        #pragma unroll 2
        for (int r = 0; r < 32; r++) {
            float4 q0 = *(const float4*)&ws[r*KTP + 12*cg];
            float4 q1 = *(const float4*)&ws[r*KTP + 12*cg + 4];
            float  q8 = ws[r*KTP + 12*cg + 8];
            ulonglong2 xv = *(const ulonglong2*)&xs[r*64 + 4*pg];
            unsigned long long xp0 = xv.x, xp1 = xv.y;
            float wv[9] = {q0.x,q0.y,q0.z,q0.w,q1.x,q1.y,q1.z,q1.w,q8};
            #pragma unroll
            for (int u = 0; u < 9; u++) {
                unsigned long long w2 = pack2(wv[u], wv[u]);
                FMA2(acc[u][0], xp0, w2);
                FMA2(acc[u][1], xp1, w2);
            }
        }
    }

    #pragma unroll
    for (int pp = 0; pp < 2; pp++) {
        float z0[9], z1[9];
        #pragma unroll
        for (int u = 0; u < 9; u++) unpack2(acc[u][pp], z0[u], z1[u]);
        #pragma unroll
        for (int half = 0; half < 2; half++) {
            float* z = half ? z1 : z0;
            float m = z[0];
            #pragma unroll
            for (int u = 1; u < 9; u++) m = fmaxf(m, z[u]);
            float e[9], s = 0.0f;
            #pragma unroll
            for (int u = 0; u < 9; u++) { e[u] = __expf((z[u]-m)*SCALE); s += e[u]; }
            float inv = 1.0f / s;
            int px = 4*pg + 2*pp + half;
            float* dst = Att + ((size_t)(n*HWP) + hw0 + px)*KTP + cg*12;
            float4 f0 = {e[0]*inv, e[1]*inv, e[2]*inv, e[3]*inv};
            float4 f1 = {e[4]*inv, e[5]*inv, e[6]*inv, e[7]*inv};
            float4 f2 = {e[8]*inv, 0.0f, 0.0f, 0.0f};
            *(float4*)(dst)     = f0;
            *(float4*)(dst + 4) = f1;
            *(float4*)(dst + 8) = f2;
        }
    }
}

// ============================================================================
// Kernel C: aggregation + fold, 5x5 collapsed stencil.
// Round-4 structure (full 192 channels per block -> ONE W2 build per
// (head,pixel), minimal att traffic) + round-5 occupancy: the fsm staging
// buffer is gone (direct STG epilogue), so smem = 96*145*8 = 111,360B and
// __launch_bounds__(384,2) gives 2 blocks/SM (24 warps).
// ============================================================================
#define AGG_SMEM_BYTES (96*145*8)                // 111360

__global__ void __launch_bounds__(384, 2) agg_kernel(
    const float* __restrict__ V, const float* __restrict__ Att,
    float* __restrict__ Fold)
{
    extern __shared__ char smraw[];
    unsigned long long* vsm2 = (unsigned long long*)smraw;      // [96][145]
    const int tid = threadIdx.x;
    const int blk = blockIdx.x;
    const int n   = blk / 49;
    const int tt  = blk - n*49;
    const int y0  = (tt / 7) * 8, x0 = (tt % 7) * 8;

    // load v window (all 192 channels as 96 channel pairs)
    for (int i = tid; i < 96*144; i += 384) {
        int cp = i / 144, pos = i - cp*144;
        int ly = pos / 12, lx = pos - ly*12;
        int gy = y0 - 2 + ly, gx = x0 - 2 + lx;
        float a = 0.0f, b = 0.0f;
        if (gy >= 0 && gy < HH && gx >= 0 && gx < WW) {
            const float* vb = &V[((size_t)(n*CC) + 2*cp)*HWP + gy*WW + gx];
            a = vb[0]; b = vb[HWP];
        }
        vsm2[cp*145 + pos] = pack2(a, b);
    }
    __syncthreads();

    {
        const int head = tid >> 6;          // 0..5
        const int q    = tid & 63;
        const int qy = q >> 3, qx = q & 7;
        const int gy = y0 + qy, gx = x0 + qx;

        // build collapsed 5x5 stencil from up to 9 neighbor att rows
        float W2[25];
        #pragma unroll
        for (int p = 0; p < 25; p++) W2[p] = 0.0f;
        #pragma unroll
        for (int i = 0; i < 3; i++)
        #pragma unroll
        for (int j = 0; j < 3; j++) {
            int py = gy + 1 - i, px = gx + 1 - j;
            if (py >= 0 && py < HH && px >= 0 && px < WW) {
                const float* ab = Att + ((size_t)n*HWP + py*WW + px)*KTP
                                      + head*108 + (i*3+j)*12;
                float4 a0 = *(const float4*)(ab);
                float4 a1 = *(const float4*)(ab + 4);
                float  a8 = ab[8];
                float av[9] = {a0.x,a0.y,a0.z,a0.w,a1.x,a1.y,a1.z,a1.w,a8};
                #pragma unroll
                for (int a = 0; a < 3; a++)
                #pragma unroll
                for (int b = 0; b < 3; b++)
                    W2[(a-i+2)*5 + (b-j+2)] += av[a*3+b];
            }
        }
        unsigned long long w22[25];
        #pragma unroll
        for (int p = 0; p < 25; p++) w22[p] = pack2(W2[p], W2[p]);

        const int pos0 = qy*12 + qx;
        float* foutbase = Fold + ((size_t)(n*CC))*HWP + gy*WW + gx;
        #pragma unroll 2
        for (int c16 = 0; c16 < 16; c16++) {
            const int cp = head*16 + c16;
            const unsigned long long* vb = vsm2 + cp*145 + pos0;
            unsigned long long acA = 0ull, acB = 0ull;
            #pragma unroll
            for (int p = 0; p < 25; p++) {
                const int off = (p/5)*12 + (p%5);
                if (p & 1) { FMA2(acB, vb[off], w22[p]); }
                else       { FMA2(acA, vb[off], w22[p]); }
            }
            float xa, ya, xb, yb;
            unpack2(acA, xa, ya); unpack2(acB, xb, yb);
            foutbase[(size_t)(2*cp    )*HWP] = xa + xb;
            foutbase[(size_t)(2*cp + 1)*HWP] = ya + yb;
        }
    }
}

// ============================================================================
// Launch
// ============================================================================
extern "C" void kernel_launch(void* const* d_in, const int* in_sizes, int n_in,
                              void* d_out, int out_size)
{
    const float* x  = (const float*)d_in[0];
    const float* Wv = (const float*)d_in[1];
    const float* Wa = (const float*)d_in[2];
    const float* ba = (const float*)d_in[3];
    const float* Wp = (const float*)d_in[4];
    const float* bp = (const float*)d_in[5];
    float* out = (float*)d_out;

    float *vp, *ap, *fp, *wpad;
    cudaGetSymbolAddress((void**)&vp, g_v);
    cudaGetSymbolAddress((void**)&ap, g_att);
    cudaGetSymbolAddress((void**)&fp, g_fold);
    cudaGetSymbolAddress((void**)&wpad, g_wpad);

    cudaFuncSetAttribute(att_kernel, cudaFuncAttributeMaxDynamicSharedMemorySize, ATT_SMEM_BYTES);
    cudaFuncSetAttribute(agg_kernel, cudaFuncAttributeMaxDynamicSharedMemorySize, AGG_SMEM_BYTES);

    // pad Wa -> [192][648]
    pad_wa_kernel<<<(CC*KTP + 255)/256, 256>>>(Wa, wpad);
    // value projection: v = x @ Wv
    gemm192_kernel<<<392*2, 192>>>(x, Wv, nullptr, vp);
    // attention logits + fused softmax (padded output)
    att_kernel<<<NB*49, 864, ATT_SMEM_BYTES>>>(x, wpad, ba, ap);
    // aggregation + fold (collapsed 5x5 stencil, 2 blocks/SM)
    agg_kernel<<<NB*49, 384, AGG_SMEM_BYTES>>>(vp, ap, fp);
    // output projection: out = folded @ Wp + bp
    gemm192_kernel<<<392*2, 192>>>(fp, Wp, bp, out);
}

// round 7
// speedup vs baseline: 1.5772x; 1.0912x over previous
#include <cuda_runtime.h>
#include <cstdint>
#include <cstddef>

#define NB    16
#define CC    192
#define HH    56
#define WW    56
#define HWP   (HH*WW)          // 3136
#define NPIX  (NB*HWP)         // 50176
#define HEADS 6
#define CHN   32
#define KT    486              // 81 * 6
#define KTP   648              // padded: 54 groups * 12
#define SCALE 0.17677669529663689f   // 32^-0.5

// ---------------- scratch (device globals; no runtime allocation) -------------
__device__ float g_v   [NB*CC*HWP];                 // value projection    (38.5 MB)
// att layout: [n][head][kout][pixel][12]  (plane-major for coalesced gather)
__device__ float g_att [(size_t)NB*HEADS*9*HWP*12]; // softmaxed att       (130 MB)
__device__ float g_fold[NB*CC*HWP];                 // folded result       (38.5 MB)
__device__ float g_wpad[CC*KTP];                    // padded Wa           (497 KB)

// ---------------- packed f32x2 helpers ---------------------------------------
#define FMA2(acc,a,b) asm("fma.rn.f32x2 %0, %1, %2, %0;" : "+l"(acc) : "l"(a), "l"(b))

__device__ __forceinline__ unsigned long long pack2(float x, float y) {
    unsigned long long r;
    asm("mov.b64 %0, {%1, %2};" : "=l"(r) : "r"(__float_as_uint(x)), "r"(__float_as_uint(y)));
    return r;
}
__device__ __forceinline__ void unpack2(unsigned long long v, float& x, float& y) {
    unsigned int lo, hi;
    asm("mov.b64 {%0, %1}, %2;" : "=r"(lo), "=r"(hi) : "l"(v));
    x = __uint_as_float(lo); y = __uint_as_float(hi);
}

// ============================================================================
// Wa pre-pad: [192][486] -> [192][648], group g's 9 cols at 12g..12g+8, pad 0.
// ============================================================================
__global__ void pad_wa_kernel(const float* __restrict__ Wa, float* __restrict__ Wp)
{
    int i = blockIdx.x * 256 + threadIdx.x;
    if (i >= CC*KTP) return;
    int c = i / KTP, col = i - c*KTP;
    int g = col / 12, u = col - g*12;
    Wp[i] = (u < 9) ? Wa[c*KT + g*9 + u] : 0.0f;
}

// ============================================================================
// Kernel A/D: 192x192 pointwise GEMM, SIMT outer-product tiling. (unchanged)
// ============================================================================
__global__ void __launch_bounds__(192, 3) gemm192_kernel(
    const float* __restrict__ X, const float* __restrict__ Wm,
    const float* __restrict__ bias, float* __restrict__ Out)
{
    __shared__ float xs[48][128];
    __shared__ float ws[48][96];
    const int tid  = threadIdx.x;
    const int b    = blockIdx.x;
    const int pt   = b >> 1;
    const int dt   = b & 1;
    const int g0   = pt * 128;
    const int dbase= dt * 96;
    const int warp = tid >> 5, lane = tid & 31;
    const int wd   = warp % 3, wp = warp / 3;
    const int ld   = lane >> 3, lp = lane & 7;
    const int d0   = wd*32 + ld*8;
    const int p0   = wp*64 + lp*8;

    unsigned long long acc[8][4];
    #pragma unroll
    for (int di = 0; di < 8; di++) {
        float bb = bias ? bias[dbase + d0 + di] : 0.0f;
        unsigned long long b2 = pack2(bb, bb);
        #pragma unroll
        for (int pp = 0; pp < 4; pp++) acc[di][pp] = b2;
    }

    for (int kc = 0; kc < 4; kc++) {
        __syncthreads();
        #pragma unroll
        for (int s = 0; s < 8; s++) {
            int idx = tid + s*192;
            int k = idx >> 5, p4 = idx & 31;
            int g = g0 + p4*4;
            int n = g / HWP, hw = g - n*HWP;
            *(float4*)&xs[k][p4*4] =
                *(const float4*)&X[((size_t)(n*CC) + kc*48 + k)*HWP + hw];
        }
        #pragma unroll
        for (int s = 0; s < 6; s++) {
            int idx = tid + s*192;
            int k = idx / 24, c4 = idx - k*24;
            *(float4*)&ws[k][c4*4] =
                *(const float4*)&Wm[(size_t)(kc*48 + k)*192 + dbase + c4*4];
        }
        __syncthreads();

        #pragma unroll 4
        for (int r = 0; r < 48; r++) {
            float4 wa = *(const float4*)&ws[r][d0];
            float4 wb = *(const float4*)&ws[r][d0+4];
            ulonglong2 xv0 = *(const ulonglong2*)&xs[r][p0];
            ulonglong2 xv1 = *(const ulonglong2*)&xs[r][p0+4];
            unsigned long long xp[4] = {xv0.x, xv0.y, xv1.x, xv1.y};
            unsigned long long w2[8];
            w2[0]=pack2(wa.x,wa.x); w2[1]=pack2(wa.y,wa.y);
            w2[2]=pack2(wa.z,wa.z); w2[3]=pack2(wa.w,wa.w);
            w2[4]=pack2(wb.x,wb.x); w2[5]=pack2(wb.y,wb.y);
            w2[6]=pack2(wb.z,wb.z); w2[7]=pack2(wb.w,wb.w);
            #pragma unroll
            for (int di = 0; di < 8; di++)
                #pragma unroll
                for (int pp = 0; pp < 4; pp++)
                    FMA2(acc[di][pp], xp[pp], w2[di]);
        }
    }

    #pragma unroll
    for (int s = 0; s < 2; s++) {
        int g = g0 + p0 + s*4;
        int n = g / HWP, hw = g - n*HWP;
        #pragma unroll
        for (int di = 0; di < 8; di++) {
            ulonglong2 uv; uv.x = acc[di][2*s]; uv.y = acc[di][2*s+1];
            *(ulonglong2*)&Out[((size_t)(n*CC) + dbase + d0 + di)*HWP + hw] = uv;
        }
    }
}

// ============================================================================
// Kernel B: attention logits GEMM + fused register softmax.
// Compute unchanged; OUTPUT now to the plane-major layout
// [n][head][kout][pixel][12]: per pixel a 48B-strided 3x STG.128 ->
// warp lanes (consecutive pixels) now coalesce into ~3 lines per 8 lanes.
// ============================================================================
#define ATT_SMEM_BYTES ((32*64 + 32*KTP)*4)      // 91136

__global__ void __launch_bounds__(864, 1) att_kernel(
    const float* __restrict__ X, const float* __restrict__ Wpad,
    const float* __restrict__ ba, float* __restrict__ Att)
{
    extern __shared__ float sm[];
    float* xs = sm;                 // [32][64]
    float* ws = sm + 32*64;         // [32][648]
    const int tid = threadIdx.x;
    const int cg  = tid >> 4;       // 0..53  (= head*9 + kout)
    const int pg  = tid & 15;       // 0..15 -> px [4pg, 4pg+4)
    const int bb  = blockIdx.x;
    const int n   = bb / 49;
    const int hw0 = (bb - n*49) * 64;

    unsigned long long acc[9][2];
    #pragma unroll
    for (int u = 0; u < 9; u++) {
        float bv = ba[9*cg + u];
        unsigned long long b2 = pack2(bv, bv);
        acc[u][0] = b2; acc[u][1] = b2;
    }

    for (int kc = 0; kc < 6; kc++) {
        __syncthreads();
        if (tid < 512) {
            int k = tid >> 4, p4 = tid & 15;
            *(float4*)&xs[k*64 + p4*4] =
                *(const float4*)&X[((size_t)(n*CC) + kc*32 + k)*HWP + hw0 + p4*4];
        }
        #pragma unroll
        for (int s = 0; s < 6; s++) {
            int idx = tid + s*864;
            int k = idx / 162, c4 = idx - k*162;
            *(float4*)&ws[k*KTP + c4*4] =
                *(const float4*)&Wpad[(size_t)(kc*32 + k)*KTP + c4*4];
        }
        __syncthreads();

        #pragma unroll 2
        for (int r = 0; r < 32; r++) {
            float4 q0 = *(const float4*)&ws[r*KTP + 12*cg];
            float4 q1 = *(const float4*)&ws[r*KTP + 12*cg + 4];
            float  q8 = ws[r*KTP + 12*cg + 8];
            ulonglong2 xv = *(const ulonglong2*)&xs[r*64 + 4*pg];
            unsigned long long xp0 = xv.x, xp1 = xv.y;
            float wv[9] = {q0.x,q0.y,q0.z,q0.w,q1.x,q1.y,q1.z,q1.w,q8};
            #pragma unroll
            for (int u = 0; u < 9; u++) {
                unsigned long long w2 = pack2(wv[u], wv[u]);
                FMA2(acc[u][0], xp0, w2);
                FMA2(acc[u][1], xp1, w2);
            }
        }
    }

    // plane base for this thread's (head,kout): plane = n*54 + cg
    float* planeBase = Att + ((size_t)n*54 + cg)*HWP*12;

    #pragma unroll
    for (int pp = 0; pp < 2; pp++) {
        float z0[9], z1[9];
        #pragma unroll
        for (int u = 0; u < 9; u++) unpack2(acc[u][pp], z0[u], z1[u]);
        #pragma unroll
        for (int half = 0; half < 2; half++) {
            float* z = half ? z1 : z0;
            float m = z[0];
            #pragma unroll
            for (int u = 1; u < 9; u++) m = fmaxf(m, z[u]);
            float e[9], s = 0.0f;
            #pragma unroll
            for (int u = 0; u < 9; u++) { e[u] = __expf((z[u]-m)*SCALE); s += e[u]; }
            float inv = 1.0f / s;
            int px = 4*pg + 2*pp + half;
            float* dst = planeBase + (size_t)(hw0 + px)*12;
            float4 f0 = {e[0]*inv, e[1]*inv, e[2]*inv, e[3]*inv};
            float4 f1 = {e[4]*inv, e[5]*inv, e[6]*inv, e[7]*inv};
            float4 f2 = {e[8]*inv, 0.0f, 0.0f, 0.0f};
            *(float4*)(dst)     = f0;
            *(float4*)(dst + 4) = f1;
            *(float4*)(dst + 8) = f2;
        }
    }
}

// ============================================================================
// Kernel C: aggregation + fold, 5x5 collapsed stencil.
// Full 192 channels per block (ONE W2 build per (head,pixel)); smem =
// 96*145*8 = 111,360B -> 2 blocks/SM. Register-safe: W2 kept as 25 FLOATS,
// packed once per p in the p-outer loop (acc[16] per chpair inner) ->
// ~65 live regs, no spills at the 84-reg cap.
// Att gather now plane-major: lanes (consecutive qx) read 48B-strided ->
// coalesced (~3 lines per 8 lanes instead of 8).
// ============================================================================
#define AGG_SMEM_BYTES (96*145*8)                // 111360

__global__ void __launch_bounds__(384, 2) agg_kernel(
    const float* __restrict__ V, const float* __restrict__ Att,
    float* __restrict__ Fold)
{
    extern __shared__ char smraw[];
    unsigned long long* vsm2 = (unsigned long long*)smraw;      // [96][145]
    const int tid = threadIdx.x;
    const int blk = blockIdx.x;
    const int n   = blk / 49;
    const int tt  = blk - n*49;
    const int y0  = (tt / 7) * 8, x0 = (tt % 7) * 8;

    // load v window (all 192 channels as 96 channel pairs)
    for (int i = tid; i < 96*144; i += 384) {
        int cp = i / 144, pos = i - cp*144;
        int ly = pos / 12, lx = pos - ly*12;
        int gy = y0 - 2 + ly, gx = x0 - 2 + lx;
        float a = 0.0f, b = 0.0f;
        if (gy >= 0 && gy < HH && gx >= 0 && gx < WW) {
            const float* vb = &V[((size_t)(n*CC) + 2*cp)*HWP + gy*WW + gx];
            a = vb[0]; b = vb[HWP];
        }
        vsm2[cp*145 + pos] = pack2(a, b);
    }
    __syncthreads();

    {
        const int head = tid >> 6;          // 0..5
        const int q    = tid & 63;
        const int qy = q >> 3, qx = q & 7;
        const int gy = y0 + qy, gx = x0 + qx;

        // build collapsed 5x5 stencil from up to 9 neighbor att rows
        float W2[25];
        #pragma unroll
        for (int p = 0; p < 25; p++) W2[p] = 0.0f;
        const float* hbase = Att + ((size_t)n*54 + head*9)*HWP*12;
        #pragma unroll
        for (int i = 0; i < 3; i++)
        #pragma unroll
        for (int j = 0; j < 3; j++) {
            int py = gy + 1 - i, px = gx + 1 - j;
            if (py >= 0 && py < HH && px >= 0 && px < WW) {
                const float* ab = hbase + ((size_t)(i*3+j)*HWP + py*WW + px)*12;
                float4 a0 = *(const float4*)(ab);
                float4 a1 = *(const float4*)(ab + 4);
                float  a8 = ab[8];
                float av[9] = {a0.x,a0.y,a0.z,a0.w,a1.x,a1.y,a1.z,a1.w,a8};
                #pragma unroll
                for (int a = 0; a < 3; a++)
                #pragma unroll
                for (int b = 0; b < 3; b++)
                    W2[(a-i+2)*5 + (b-j+2)] += av[a*3+b];
            }
        }

        // p-outer / chpair-inner: pack each weight ONCE, 16 independent accs
        unsigned long long acc[16];
        #pragma unroll
        for (int c16 = 0; c16 < 16; c16++) acc[c16] = 0ull;
        const unsigned long long* vbase = vsm2 + (head*16)*145 + qy*12 + qx;
        #pragma unroll
        for (int p = 0; p < 25; p++) {
            const int off = (p/5)*12 + (p%5);
            unsigned long long w2 = pack2(W2[p], W2[p]);
            #pragma unroll
            for (int c16 = 0; c16 < 16; c16++)
                FMA2(acc[c16], vbase[c16*145 + off], w2);
        }

        float* foutbase = Fold + ((size_t)(n*CC))*HWP + gy*WW + gx;
        #pragma unroll
        for (int c16 = 0; c16 < 16; c16++) {
            const int cp = head*16 + c16;
            float xa, ya;
            unpack2(acc[c16], xa, ya);
            foutbase[(size_t)(2*cp    )*HWP] = xa;
            foutbase[(size_t)(2*cp + 1)*HWP] = ya;
        }
    }
}

// ============================================================================
// Launch
// ============================================================================
extern "C" void kernel_launch(void* const* d_in, const int* in_sizes, int n_in,
                              void* d_out, int out_size)
{
    const float* x  = (const float*)d_in[0];
    const float* Wv = (const float*)d_in[1];
    const float* Wa = (const float*)d_in[2];
    const float* ba = (const float*)d_in[3];
    const float* Wp = (const float*)d_in[4];
    const float* bp = (const float*)d_in[5];
    float* out = (float*)d_out;

    float *vp, *ap, *fp, *wpad;
    cudaGetSymbolAddress((void**)&vp, g_v);
    cudaGetSymbolAddress((void**)&ap, g_att);
    cudaGetSymbolAddress((void**)&fp, g_fold);
    cudaGetSymbolAddress((void**)&wpad, g_wpad);

    cudaFuncSetAttribute(att_kernel, cudaFuncAttributeMaxDynamicSharedMemorySize, ATT_SMEM_BYTES);
    cudaFuncSetAttribute(agg_kernel, cudaFuncAttributeMaxDynamicSharedMemorySize, AGG_SMEM_BYTES);

    // pad Wa -> [192][648]
    pad_wa_kernel<<<(CC*KTP + 255)/256, 256>>>(Wa, wpad);
    // value projection: v = x @ Wv
    gemm192_kernel<<<392*2, 192>>>(x, Wv, nullptr, vp);
    // attention logits + fused softmax (plane-major output)
    att_kernel<<<NB*49, 864, ATT_SMEM_BYTES>>>(x, wpad, ba, ap);
    // aggregation + fold (collapsed 5x5 stencil, coalesced att gather)
    agg_kernel<<<NB*49, 384, AGG_SMEM_BYTES>>>(vp, ap, fp);
    // output projection: out = folded @ Wp + bp
    gemm192_kernel<<<392*2, 192>>>(fp, Wp, bp, out);
}

// round 8
// speedup vs baseline: 1.6544x; 1.0490x over previous
#include <cuda_runtime.h>
#include <cuda_fp16.h>
#include <cstdint>
#include <cstddef>

#define NB    16
#define CC    192
#define HH    56
#define WW    56
#define HWP   (HH*WW)          // 3136
#define NPIX  (NB*HWP)         // 50176
#define HEADS 6
#define CHN   32
#define KT    486              // 81 * 6
#define KTP   648              // padded: 54 groups * 12
#define SCALE 0.17677669529663689f   // 32^-0.5

// ---------------- scratch (device globals; no runtime allocation) -------------
__device__ float  g_v   [NB*CC*HWP];                 // value projection    (38.5 MB)
// att layout: [n][head][kout][pixel][12] in FP16 (65 MB, plane-major)
__device__ __half g_att [(size_t)NB*HEADS*9*HWP*12];
__device__ float  g_fold[NB*CC*HWP];                 // folded result       (38.5 MB)
__device__ float  g_wpad[CC*KTP];                    // padded Wa           (497 KB)

// ---------------- packed f32x2 helpers ---------------------------------------
#define FMA2(acc,a,b) asm("fma.rn.f32x2 %0, %1, %2, %0;" : "+l"(acc) : "l"(a), "l"(b))

__device__ __forceinline__ unsigned long long pack2(float x, float y) {
    unsigned long long r;
    asm("mov.b64 %0, {%1, %2};" : "=l"(r) : "r"(__float_as_uint(x)), "r"(__float_as_uint(y)));
    return r;
}
__device__ __forceinline__ void unpack2(unsigned long long v, float& x, float& y) {
    unsigned int lo, hi;
    asm("mov.b64 {%0, %1}, %2;" : "=r"(lo), "=r"(hi) : "l"(v));
    x = __uint_as_float(lo); y = __uint_as_float(hi);
}

// ============================================================================
// Wa pre-pad: [192][486] -> [192][648], group g's 9 cols at 12g..12g+8, pad 0.
// ============================================================================
__global__ void pad_wa_kernel(const float* __restrict__ Wa, float* __restrict__ Wp)
{
    int i = blockIdx.x * 256 + threadIdx.x;
    if (i >= CC*KTP) return;
    int c = i / KTP, col = i - c*KTP;
    int g = col / 12, u = col - g*12;
    Wp[i] = (u < 9) ? Wa[c*KT + g*9 + u] : 0.0f;
}

// ============================================================================
// Kernel A/D: 192x192 pointwise GEMM, SIMT outer-product tiling. (unchanged)
// ============================================================================
__global__ void __launch_bounds__(192, 3) gemm192_kernel(
    const float* __restrict__ X, const float* __restrict__ Wm,
    const float* __restrict__ bias, float* __restrict__ Out)
{
    __shared__ float xs[48][128];
    __shared__ float ws[48][96];
    const int tid  = threadIdx.x;
    const int b    = blockIdx.x;
    const int pt   = b >> 1;
    const int dt   = b & 1;
    const int g0   = pt * 128;
    const int dbase= dt * 96;
    const int warp = tid >> 5, lane = tid & 31;
    const int wd   = warp % 3, wp = warp / 3;
    const int ld   = lane >> 3, lp = lane & 7;
    const int d0   = wd*32 + ld*8;
    const int p0   = wp*64 + lp*8;

    unsigned long long acc[8][4];
    #pragma unroll
    for (int di = 0; di < 8; di++) {
        float bb = bias ? bias[dbase + d0 + di] : 0.0f;
        unsigned long long b2 = pack2(bb, bb);
        #pragma unroll
        for (int pp = 0; pp < 4; pp++) acc[di][pp] = b2;
    }

    for (int kc = 0; kc < 4; kc++) {
        __syncthreads();
        #pragma unroll
        for (int s = 0; s < 8; s++) {
            int idx = tid + s*192;
            int k = idx >> 5, p4 = idx & 31;
            int g = g0 + p4*4;
            int n = g / HWP, hw = g - n*HWP;
            *(float4*)&xs[k][p4*4] =
                *(const float4*)&X[((size_t)(n*CC) + kc*48 + k)*HWP + hw];
        }
        #pragma unroll
        for (int s = 0; s < 6; s++) {
            int idx = tid + s*192;
            int k = idx / 24, c4 = idx - k*24;
            *(float4*)&ws[k][c4*4] =
                *(const float4*)&Wm[(size_t)(kc*48 + k)*192 + dbase + c4*4];
        }
        __syncthreads();

        #pragma unroll 4
        for (int r = 0; r < 48; r++) {
            float4 wa = *(const float4*)&ws[r][d0];
            float4 wb = *(const float4*)&ws[r][d0+4];
            ulonglong2 xv0 = *(const ulonglong2*)&xs[r][p0];
            ulonglong2 xv1 = *(const ulonglong2*)&xs[r][p0+4];
            unsigned long long xp[4] = {xv0.x, xv0.y, xv1.x, xv1.y};
            unsigned long long w2[8];
            w2[0]=pack2(wa.x,wa.x); w2[1]=pack2(wa.y,wa.y);
            w2[2]=pack2(wa.z,wa.z); w2[3]=pack2(wa.w,wa.w);
            w2[4]=pack2(wb.x,wb.x); w2[5]=pack2(wb.y,wb.y);
            w2[6]=pack2(wb.z,wb.z); w2[7]=pack2(wb.w,wb.w);
            #pragma unroll
            for (int di = 0; di < 8; di++)
                #pragma unroll
                for (int pp = 0; pp < 4; pp++)
                    FMA2(acc[di][pp], xp[pp], w2[di]);
        }
    }

    #pragma unroll
    for (int s = 0; s < 2; s++) {
        int g = g0 + p0 + s*4;
        int n = g / HWP, hw = g - n*HWP;
        #pragma unroll
        for (int di = 0; di < 8; di++) {
            ulonglong2 uv; uv.x = acc[di][2*s]; uv.y = acc[di][2*s+1];
            *(ulonglong2*)&Out[((size_t)(n*CC) + dbase + d0 + di)*HWP + hw] = uv;
        }
    }
}

// ============================================================================
// Kernel B: attention logits GEMM + fused register softmax.
// Compute in fp32 (unchanged); OUTPUT now FP16 to the plane-major layout
// [n][head][kout][pixel][12]: 24B per (pixel,group), 3x STG.64.
// ============================================================================
#define ATT_SMEM_BYTES ((32*64 + 32*KTP)*4)      // 91136

__global__ void __launch_bounds__(864, 1) att_kernel(
    const float* __restrict__ X, const float* __restrict__ Wpad,
    const float* __restrict__ ba, __half* __restrict__ Att)
{
    extern __shared__ float sm[];
    float* xs = sm;                 // [32][64]
    float* ws = sm + 32*64;         // [32][648]
    const int tid = threadIdx.x;
    const int cg  = tid >> 4;       // 0..53  (= head*9 + kout)
    const int pg  = tid & 15;       // 0..15 -> px [4pg, 4pg+4)
    const int bb  = blockIdx.x;
    const int n   = bb / 49;
    const int hw0 = (bb - n*49) * 64;

    unsigned long long acc[9][2];
    #pragma unroll
    for (int u = 0; u < 9; u++) {
        float bv = ba[9*cg + u];
        unsigned long long b2 = pack2(bv, bv);
        acc[u][0] = b2; acc[u][1] = b2;
    }

    for (int kc = 0; kc < 6; kc++) {
        __syncthreads();
        if (tid < 512) {
            int k = tid >> 4, p4 = tid & 15;
            *(float4*)&xs[k*64 + p4*4] =
                *(const float4*)&X[((size_t)(n*CC) + kc*32 + k)*HWP + hw0 + p4*4];
        }
        #pragma unroll
        for (int s = 0; s < 6; s++) {
            int idx = tid + s*864;
            int k = idx / 162, c4 = idx - k*162;
            *(float4*)&ws[k*KTP + c4*4] =
                *(const float4*)&Wpad[(size_t)(kc*32 + k)*KTP + c4*4];
        }
        __syncthreads();

        #pragma unroll 2
        for (int r = 0; r < 32; r++) {
            float4 q0 = *(const float4*)&ws[r*KTP + 12*cg];
            float4 q1 = *(const float4*)&ws[r*KTP + 12*cg + 4];
            float  q8 = ws[r*KTP + 12*cg + 8];
            ulonglong2 xv = *(const ulonglong2*)&xs[r*64 + 4*pg];
            unsigned long long xp0 = xv.x, xp1 = xv.y;
            float wv[9] = {q0.x,q0.y,q0.z,q0.w,q1.x,q1.y,q1.z,q1.w,q8};
            #pragma unroll
            for (int u = 0; u < 9; u++) {
                unsigned long long w2 = pack2(wv[u], wv[u]);
                FMA2(acc[u][0], xp0, w2);
                FMA2(acc[u][1], xp1, w2);
            }
        }
    }

    // plane base for this thread's (head,kout): plane = n*54 + cg
    __half* planeBase = Att + ((size_t)n*54 + cg)*HWP*12;

    #pragma unroll
    for (int pp = 0; pp < 2; pp++) {
        float z0[9], z1[9];
        #pragma unroll
        for (int u = 0; u < 9; u++) unpack2(acc[u][pp], z0[u], z1[u]);
        #pragma unroll
        for (int half = 0; half < 2; half++) {
            float* z = half ? z1 : z0;
            float m = z[0];
            #pragma unroll
            for (int u = 1; u < 9; u++) m = fmaxf(m, z[u]);
            float e[9], s = 0.0f;
            #pragma unroll
            for (int u = 0; u < 9; u++) { e[u] = __expf((z[u]-m)*SCALE); s += e[u]; }
            float inv = 1.0f / s;
            int px = 4*pg + 2*pp + half;
            __half* dst = planeBase + (size_t)(hw0 + px)*12;
            __half2 h01 = __floats2half2_rn(e[0]*inv, e[1]*inv);
            __half2 h23 = __floats2half2_rn(e[2]*inv, e[3]*inv);
            __half2 h45 = __floats2half2_rn(e[4]*inv, e[5]*inv);
            __half2 h67 = __floats2half2_rn(e[6]*inv, e[7]*inv);
            __half2 h8x = __floats2half2_rn(e[8]*inv, 0.0f);
            __half2 hxx = __floats2half2_rn(0.0f, 0.0f);
            uint2 u0, u1, u2;
            u0.x = *(unsigned int*)&h01; u0.y = *(unsigned int*)&h23;
            u1.x = *(unsigned int*)&h45; u1.y = *(unsigned int*)&h67;
            u2.x = *(unsigned int*)&h8x; u2.y = *(unsigned int*)&hxx;
            *(uint2*)(dst)     = u0;
            *(uint2*)(dst + 4) = u1;
            *(uint2*)(dst + 8) = u2;
        }
    }
}

// ============================================================================
// Kernel C: aggregation + fold, 5x5 collapsed stencil.
// Full 192 channels per block (ONE W2 build per (head,pixel)); smem =
// 96*145*8 = 111,360B -> 2 blocks/SM. att gather now FP16 plane-major:
// 24B per (neighbor,group) as 3x LDG.64, converted to fp32 once and folded
// into the 25-float collapsed stencil. Inner loop unchanged (fp32 f32x2).
// ============================================================================
#define AGG_SMEM_BYTES (96*145*8)                // 111360

__global__ void __launch_bounds__(384, 2) agg_kernel(
    const float* __restrict__ V, const __half* __restrict__ Att,
    float* __restrict__ Fold)
{
    extern __shared__ char smraw[];
    unsigned long long* vsm2 = (unsigned long long*)smraw;      // [96][145]
    const int tid = threadIdx.x;
    const int blk = blockIdx.x;
    const int n   = blk / 49;
    const int tt  = blk - n*49;
    const int y0  = (tt / 7) * 8, x0 = (tt % 7) * 8;

    // load v window (all 192 channels as 96 channel pairs)
    for (int i = tid; i < 96*144; i += 384) {
        int cp = i / 144, pos = i - cp*144;
        int ly = pos / 12, lx = pos - ly*12;
        int gy = y0 - 2 + ly, gx = x0 - 2 + lx;
        float a = 0.0f, b = 0.0f;
        if (gy >= 0 && gy < HH && gx >= 0 && gx < WW) {
            const float* vb = &V[((size_t)(n*CC) + 2*cp)*HWP + gy*WW + gx];
            a = vb[0]; b = vb[HWP];
        }
        vsm2[cp*145 + pos] = pack2(a, b);
    }
    __syncthreads();

    {
        const int head = tid >> 6;          // 0..5
        const int q    = tid & 63;
        const int qy = q >> 3, qx = q & 7;
        const int gy = y0 + qy, gx = x0 + qx;

        // build collapsed 5x5 stencil from up to 9 neighbor att rows (fp16)
        float W2[25];
        #pragma unroll
        for (int p = 0; p < 25; p++) W2[p] = 0.0f;
        const __half* hbase = Att + ((size_t)n*54 + head*9)*HWP*12;
        #pragma unroll
        for (int i = 0; i < 3; i++)
        #pragma unroll
        for (int j = 0; j < 3; j++) {
            int py = gy + 1 - i, px = gx + 1 - j;
            if (py >= 0 && py < HH && px >= 0 && px < WW) {
                const __half* ab = hbase + ((size_t)(i*3+j)*HWP + py*WW + px)*12;
                uint2 u0 = *(const uint2*)(ab);
                uint2 u1 = *(const uint2*)(ab + 4);
                unsigned int u2 = *(const unsigned int*)(ab + 8);
                __half2 h01 = *(__half2*)&u0.x, h23 = *(__half2*)&u0.y;
                __half2 h45 = *(__half2*)&u1.x, h67 = *(__half2*)&u1.y;
                __half2 h8x = *(__half2*)&u2;
                float2 f01 = __half22float2(h01);
                float2 f23 = __half22float2(h23);
                float2 f45 = __half22float2(h45);
                float2 f67 = __half22float2(h67);
                float  f8  = __low2float(h8x);
                float av[9] = {f01.x, f01.y, f23.x, f23.y,
                               f45.x, f45.y, f67.x, f67.y, f8};
                #pragma unroll
                for (int a = 0; a < 3; a++)
                #pragma unroll
                for (int b = 0; b < 3; b++)
                    W2[(a-i+2)*5 + (b-j+2)] += av[a*3+b];
            }
        }

        // p-outer / chpair-inner: pack each weight ONCE, 16 independent accs
        unsigned long long acc[16];
        #pragma unroll
        for (int c16 = 0; c16 < 16; c16++) acc[c16] = 0ull;
        const unsigned long long* vbase = vsm2 + (head*16)*145 + qy*12 + qx;
        #pragma unroll
        for (int p = 0; p < 25; p++) {
            const int off = (p/5)*12 + (p%5);
            unsigned long long w2 = pack2(W2[p], W2[p]);
            #pragma unroll
            for (int c16 = 0; c16 < 16; c16++)
                FMA2(acc[c16], vbase[c16*145 + off], w2);
        }

        float* foutbase = Fold + ((size_t)(n*CC))*HWP + gy*WW + gx;
        #pragma unroll
        for (int c16 = 0; c16 < 16; c16++) {
            const int cp = head*16 + c16;
            float xa, ya;
            unpack2(acc[c16], xa, ya);
            foutbase[(size_t)(2*cp    )*HWP] = xa;
            foutbase[(size_t)(2*cp + 1)*HWP] = ya;
        }
    }
}

// ============================================================================
// Launch
// ============================================================================
extern "C" void kernel_launch(void* const* d_in, const int* in_sizes, int n_in,
                              void* d_out, int out_size)
{
    const float* x  = (const float*)d_in[0];
    const float* Wv = (const float*)d_in[1];
    const float* Wa = (const float*)d_in[2];
    const float* ba = (const float*)d_in[3];
    const float* Wp = (const float*)d_in[4];
    const float* bp = (const float*)d_in[5];
    float* out = (float*)d_out;

    float *vp, *fp, *wpad;
    __half* ap;
    cudaGetSymbolAddress((void**)&vp, g_v);
    cudaGetSymbolAddress((void**)&ap, g_att);
    cudaGetSymbolAddress((void**)&fp, g_fold);
    cudaGetSymbolAddress((void**)&wpad, g_wpad);

    cudaFuncSetAttribute(att_kernel, cudaFuncAttributeMaxDynamicSharedMemorySize, ATT_SMEM_BYTES);
    cudaFuncSetAttribute(agg_kernel, cudaFuncAttributeMaxDynamicSharedMemorySize, AGG_SMEM_BYTES);

    // pad Wa -> [192][648]
    pad_wa_kernel<<<(CC*KTP + 255)/256, 256>>>(Wa, wpad);
    // value projection: v = x @ Wv
    gemm192_kernel<<<392*2, 192>>>(x, Wv, nullptr, vp);
    // attention logits + fused softmax (fp16 plane-major output)
    att_kernel<<<NB*49, 864, ATT_SMEM_BYTES>>>(x, wpad, ba, ap);
    // aggregation + fold (collapsed 5x5 stencil, fp16 att gather)
    agg_kernel<<<NB*49, 384, AGG_SMEM_BYTES>>>(vp, ap, fp);
    // output projection: out = folded @ Wp + bp
    gemm192_kernel<<<392*2, 192>>>(fp, Wp, bp, out);
}